// round 13
// baseline (speedup 1.0000x reference)
#include <cuda_runtime.h>
#include <cstdint>

#define N_ATOMS 1024
#define NSHIFT 27
#define CUT2 25.0f                      // CUTOFF^2

#define ITILE 16                        // i-rows per block
#define JTILE 32                        // j-atoms per block
#define BTHREADS 256
#define PAIRS_TILE (JTILE * NSHIFT)     // 864 pairs per row segment
#define UNITS (PAIRS_TILE / 4)          // 216 units of 4 pairs (12 floats)
#define SEG_FLOATS (PAIRS_TILE * 3)     // 2592 floats
#define SEG_BYTES (SEG_FLOATS * 4)      // 10368 B per TMA op (16B multiple)
#define NBUF 3                          // 3-deep pipeline -> 31.1 KB smem,
                                        // 7 blocks/SM resident (was 5)

// R7 structure with NBUF=3: register-resident B vectors (one 4-pair unit per
// thread), STS.128 staging, 3-deep pipelined cp.async.bulk stores
// (wait_group 2), higher resident-CTA concurrency.
__global__ void __launch_bounds__(BTHREADS)
radius_out(const float* __restrict__ frac,
           const float* __restrict__ cell,
           float* __restrict__ out) {
    __shared__ __align__(16) float buf[NBUF][SEG_FLOATS];   // 3 x 10368 B

    const int j0  = blockIdx.x * JTILE;    // x = j-segment: consecutive blocks
    const int i0  = blockIdx.y * ITILE;    //     write adjacent GMEM bands
    const int tid = threadIdx.x;
    const bool active = tid < UNITS;       // one 4-pair unit per thread

    float c[9];
#pragma unroll
    for (int m = 0; m < 9; m++) c[m] = __ldg(cell + m);

    // Per-thread B vectors for pairs 4*tid .. 4*tid+3.
    // B[p] = cart[j0 + p/27] + shift(p%27) @ cell, identical FP order to ref.
    float Bx[4], By[4], Bz[4];
    if (active) {
#pragma unroll
        for (int q = 0; q < 4; q++) {
            int p = 4 * tid + q;
            int j = p / NSHIFT;
            int s = p - NSHIFT * j;
            float f0 = __ldg(frac + 3 * (j0 + j) + 0);
            float f1 = __ldg(frac + 3 * (j0 + j) + 1);
            float f2 = __ldg(frac + 3 * (j0 + j) + 2);
            float sx = (float)(s / 9 - 1);
            float sy = (float)((s / 3) % 3 - 1);
            float sz = (float)(s % 3 - 1);
            float cj[3], sc[3];
#pragma unroll
            for (int m = 0; m < 3; m++) {
                cj[m] = fmaf(f2, c[6 + m], fmaf(f1, c[3 + m], f0 * c[m]));
                sc[m] = fmaf(sz, c[6 + m], fmaf(sy, c[3 + m], sx * c[m]));
            }
            Bx[q] = __fadd_rn(cj[0], sc[0]);
            By[q] = __fadd_rn(cj[1], sc[1]);
            Bz[q] = __fadd_rn(cj[2], sc[2]);
        }
    }

#pragma unroll 1
    for (int r = 0; r < ITILE; r++) {
        const int b = r % NBUF;
        const int i = i0 + r;

        // Buffer b was handed to a bulk group at iteration r-3; wait_group 2
        // allows the 2 younger groups to stay in flight.
        if (r >= NBUF) {
            if (tid == 0)
                asm volatile("cp.async.bulk.wait_group 2;" ::: "memory");
            __syncthreads();
        }

        // cart[i], same fmaf chain as reference (broadcast loads)
        float g0 = __ldg(frac + 3 * i + 0);
        float g1 = __ldg(frac + 3 * i + 1);
        float g2 = __ldg(frac + 3 * i + 2);
        float cix = fmaf(g2, c[6], fmaf(g1, c[3], g0 * c[0]));
        float ciy = fmaf(g2, c[7], fmaf(g1, c[4], g0 * c[1]));
        float ciz = fmaf(g2, c[8], fmaf(g1, c[5], g0 * c[2]));

        if (active) {
            float o[12];
#pragma unroll
            for (int q = 0; q < 4; q++) {
                float dx = __fadd_rn(Bx[q], -cix);
                float dy = __fadd_rn(By[q], -ciy);
                float dz = __fadd_rn(Bz[q], -ciz);
                float d2 = __fadd_rn(__fadd_rn(__fmul_rn(dx, dx),
                                               __fmul_rn(dy, dy)),
                                     __fmul_rn(dz, dz));
                bool keep = d2 < CUT2;      // self-edge yields +0 anyway
                o[3 * q + 0] = keep ? dx : 0.0f;
                o[3 * q + 1] = keep ? dy : 0.0f;
                o[3 * q + 2] = keep ? dz : 0.0f;
            }
            // 12 consecutive floats -> 3x STS.128, 16B-aligned (48B/thread)
            float4* dst = (float4*)&buf[b][12 * tid];
            dst[0] = make_float4(o[0], o[1],  o[2],  o[3]);
            dst[1] = make_float4(o[4], o[5],  o[6],  o[7]);
            dst[2] = make_float4(o[8], o[9],  o[10], o[11]);
        }
        __syncthreads();

        if (tid == 0) {
            asm volatile("fence.proxy.async.shared::cta;" ::: "memory");
            // contiguous 10368B segment: out[(i*1024 + j0)*81 ...]
            float* gdst = out + (size_t)((size_t)i * N_ATOMS + (size_t)j0) * 81u;
            uint32_t ssrc = (uint32_t)__cvta_generic_to_shared(&buf[b][0]);
            asm volatile(
                "cp.async.bulk.global.shared::cta.bulk_group [%0], [%1], %2;"
                :: "l"(gdst), "r"(ssrc), "r"((uint32_t)SEG_BYTES)
                : "memory");
            asm volatile("cp.async.bulk.commit_group;" ::: "memory");
        }
    }

    // Drain all outstanding bulk stores before SMEM is released.
    if (tid == 0)
        asm volatile("cp.async.bulk.wait_group 0;" ::: "memory");
}

extern "C" void kernel_launch(void* const* d_in, const int* in_sizes, int n_in,
                              void* d_out, int out_size) {
    const float* frac = (const float*)d_in[0];   // [1024,3]
    const float* cell = (const float*)d_in[1];   // [3,3]
    float* out = (float*)d_out;                  // [1024,1024,27,3]

    dim3 grid(N_ATOMS / JTILE, N_ATOMS / ITILE); // (32, 64) = 2048 blocks
    radius_out<<<grid, BTHREADS>>>(frac, cell, out);
}

// round 14
// speedup vs baseline: 1.0552x; 1.0552x over previous
#include <cuda_runtime.h>
#include <cstdint>

#define N_ATOMS 1024
#define NSHIFT 27
#define CUT2 25.0f                      // CUTOFF^2

#define ITILE 16                        // i-rows per block
#define JTILE 32                        // j-atoms per block
#define BTHREADS 256
#define PAIRS_TILE (JTILE * NSHIFT)     // 864 pairs per row segment
#define UNITS (PAIRS_TILE / 4)          // 216 units of 4 pairs (12 floats)
#define SEG_FLOATS (PAIRS_TILE * 3)     // 2592 floats
#define SEG_BYTES (SEG_FLOATS * 4)      // 10368 B per TMA op (16B multiple)
#define NBUF 4                          // 4-deep store pipeline

// Final kernel (session-best e2e, R7 configuration): register-resident B
// vectors (one 4-pair unit per thread), STS.128 SMEM staging, 4-deep
// pipelined cp.async.bulk stores (wait_group 3). Pinned at the
// path-independent L2/DRAM pure-write acceptance floor.
__global__ void __launch_bounds__(BTHREADS)
radius_out(const float* __restrict__ frac,
           const float* __restrict__ cell,
           float* __restrict__ out) {
    __shared__ __align__(16) float buf[NBUF][SEG_FLOATS];   // 4 x 10368 B

    const int j0  = blockIdx.x * JTILE;    // x = j-segment: consecutive blocks
    const int i0  = blockIdx.y * ITILE;    //     write adjacent GMEM bands
    const int tid = threadIdx.x;
    const bool active = tid < UNITS;       // one 4-pair unit per thread

    float c[9];
#pragma unroll
    for (int m = 0; m < 9; m++) c[m] = __ldg(cell + m);

    // Per-thread B vectors for pairs 4*tid .. 4*tid+3.
    // B[p] = cart[j0 + p/27] + shift(p%27) @ cell, identical FP order to ref.
    float Bx[4], By[4], Bz[4];
    if (active) {
#pragma unroll
        for (int q = 0; q < 4; q++) {
            int p = 4 * tid + q;
            int j = p / NSHIFT;
            int s = p - NSHIFT * j;
            float f0 = __ldg(frac + 3 * (j0 + j) + 0);
            float f1 = __ldg(frac + 3 * (j0 + j) + 1);
            float f2 = __ldg(frac + 3 * (j0 + j) + 2);
            float sx = (float)(s / 9 - 1);
            float sy = (float)((s / 3) % 3 - 1);
            float sz = (float)(s % 3 - 1);
            float cj[3], sc[3];
#pragma unroll
            for (int m = 0; m < 3; m++) {
                cj[m] = fmaf(f2, c[6 + m], fmaf(f1, c[3 + m], f0 * c[m]));
                sc[m] = fmaf(sz, c[6 + m], fmaf(sy, c[3 + m], sx * c[m]));
            }
            Bx[q] = __fadd_rn(cj[0], sc[0]);
            By[q] = __fadd_rn(cj[1], sc[1]);
            Bz[q] = __fadd_rn(cj[2], sc[2]);
        }
    }

#pragma unroll 1
    for (int r = 0; r < ITILE; r++) {
        const int b = r & (NBUF - 1);
        const int i = i0 + r;

        // Buffer b was handed to a bulk group at iteration r-4; with
        // wait_group 3 (allow 3 younger groups in flight) this rarely blocks.
        if (r >= NBUF) {
            if (tid == 0)
                asm volatile("cp.async.bulk.wait_group 3;" ::: "memory");
            __syncthreads();
        }

        // cart[i], same fmaf chain as reference (broadcast loads)
        float g0 = __ldg(frac + 3 * i + 0);
        float g1 = __ldg(frac + 3 * i + 1);
        float g2 = __ldg(frac + 3 * i + 2);
        float cix = fmaf(g2, c[6], fmaf(g1, c[3], g0 * c[0]));
        float ciy = fmaf(g2, c[7], fmaf(g1, c[4], g0 * c[1]));
        float ciz = fmaf(g2, c[8], fmaf(g1, c[5], g0 * c[2]));

        if (active) {
            float o[12];
#pragma unroll
            for (int q = 0; q < 4; q++) {
                float dx = __fadd_rn(Bx[q], -cix);
                float dy = __fadd_rn(By[q], -ciy);
                float dz = __fadd_rn(Bz[q], -ciz);
                float d2 = __fadd_rn(__fadd_rn(__fmul_rn(dx, dx),
                                               __fmul_rn(dy, dy)),
                                     __fmul_rn(dz, dz));
                bool keep = d2 < CUT2;      // self-edge yields +0 anyway
                o[3 * q + 0] = keep ? dx : 0.0f;
                o[3 * q + 1] = keep ? dy : 0.0f;
                o[3 * q + 2] = keep ? dz : 0.0f;
            }
            // 12 consecutive floats -> 3x STS.128, 16B-aligned (48B/thread)
            float4* dst = (float4*)&buf[b][12 * tid];
            dst[0] = make_float4(o[0], o[1],  o[2],  o[3]);
            dst[1] = make_float4(o[4], o[5],  o[6],  o[7]);
            dst[2] = make_float4(o[8], o[9],  o[10], o[11]);
        }
        __syncthreads();

        if (tid == 0) {
            asm volatile("fence.proxy.async.shared::cta;" ::: "memory");
            // contiguous 10368B segment: out[(i*1024 + j0)*81 ...]
            float* gdst = out + (size_t)((size_t)i * N_ATOMS + (size_t)j0) * 81u;
            uint32_t ssrc = (uint32_t)__cvta_generic_to_shared(&buf[b][0]);
            asm volatile(
                "cp.async.bulk.global.shared::cta.bulk_group [%0], [%1], %2;"
                :: "l"(gdst), "r"(ssrc), "r"((uint32_t)SEG_BYTES)
                : "memory");
            asm volatile("cp.async.bulk.commit_group;" ::: "memory");
        }
    }

    // Drain all outstanding bulk stores before SMEM is released.
    if (tid == 0)
        asm volatile("cp.async.bulk.wait_group 0;" ::: "memory");
}

extern "C" void kernel_launch(void* const* d_in, const int* in_sizes, int n_in,
                              void* d_out, int out_size) {
    const float* frac = (const float*)d_in[0];   // [1024,3]
    const float* cell = (const float*)d_in[1];   // [3,3]
    float* out = (float*)d_out;                  // [1024,1024,27,3]

    dim3 grid(N_ATOMS / JTILE, N_ATOMS / ITILE); // (32, 64) = 2048 blocks
    radius_out<<<grid, BTHREADS>>>(frac, cell, out);
}